// round 14
// baseline (speedup 1.0000x reference)
#include <cuda_runtime.h>

#define NQ     10
#define NL     4
#define WPB    4
#define BLOCK  (32 * WPB)

typedef unsigned long long u64;

// Per gate: 4 role-combos (rlo,rhi) x 6 packs {ARe,AIm,AImN,BRe,BIm,BImN}
__device__   u64 gPackedBuf[NL * NQ * 24];
__constant__ u64 cG[NL * NQ * 24];
// Layer-0 fused matrices, plain floats: {M00x,M00y,M01x,M01y,M10x,M10y,M11x,M11y}
__device__   float gM0Buf[NQ * 8];
__constant__ float cM0[NQ * 8];

// ============================================================
// Compile-time GF(2) frame tables (semantics verified R8-R13)
// ============================================================
__host__ __device__ constexpr int parc(int v) {
    int c = 0;
    for (int b = 0; b < NQ; ++b) c ^= (v >> b) & 1;
    return c;
}

constexpr int sigma1(int j) {
    int s = j;
    for (int q = 9; q >= 0; --q) {
        int pc = 9 - q;
        int pt = 9 - ((q + 1) % 10);
        s ^= ((s >> pc) & 1) << pt;
    }
    return s;
}

struct MaskTab {
    int m[NL][NQ];
    int sel[NL + 1][NQ];
};

constexpr MaskTab build_masks() {
    MaskTab t{};
    int perm[1024] = {};
    for (int j = 0; j < 1024; ++j) perm[j] = j;
    int inv[1024] = {};
    for (int l = 0; l <= NL; ++l) {
        if (l < NL)
            for (int p = 0; p < NQ; ++p) t.m[l][p] = perm[1 << p];
        for (int j = 0; j < 1024; ++j) inv[perm[j]] = j;
        for (int p = 0; p < NQ; ++p) {
            int s = 0;
            for (int b = 0; b < NQ; ++b) s |= ((inv[1 << b] >> p) & 1) << b;
            t.sel[l][p] = s;
        }
        if (l < NL) {
            int nxt[1024] = {};
            for (int j = 0; j < 1024; ++j) nxt[j] = perm[sigma1(j)];
            for (int j = 0; j < 1024; ++j) perm[j] = nxt[j];
        }
    }
    return t;
}
constexpr MaskTab MT = build_masks();

// ============================================================
// Packed f32x2 helpers
// ============================================================
__device__ __forceinline__ u64 pk2(float a, float b) {
    u64 r; asm("mov.b64 %0, {%1, %2};" : "=l"(r) : "f"(a), "f"(b)); return r;
}
__device__ __forceinline__ void upk(u64 v, float& a, float& b) {
    asm("mov.b64 {%0, %1}, %2;" : "=f"(a), "=f"(b) : "l"(v));
}
__device__ __forceinline__ u64 fma2(u64 a, u64 b, u64 c) {
    u64 d; asm("fma.rn.f32x2 %0, %1, %2, %3;" : "=l"(d) : "l"(a), "l"(b), "l"(c)); return d;
}
__device__ __forceinline__ u64 mul2(u64 a, u64 b) {
    u64 d; asm("mul.rn.f32x2 %0, %1, %2;" : "=l"(d) : "l"(a), "l"(b)); return d;
}
__device__ __forceinline__ u64 swap64(u64 v) {
    union { u64 w; uint2 u; } a;
    a.w = v;
    unsigned t = a.u.x; a.u.x = a.u.y; a.u.y = t;
    return a.w;
}
__device__ __forceinline__ u64 shfl64x(u64 v, int xm) {
    return __shfl_xor_sync(0xffffffffu, v, xm);
}

// ============================================================
// Setup: fuse Rx*Ry*Rz; packs for all gates + raw M for layer 0
// ============================================================
struct c2 { float x, y; };
__device__ __forceinline__ c2 cmulh(c2 a, c2 b) { return { a.x*b.x - a.y*b.y, a.x*b.y + a.y*b.x }; }
__device__ __forceinline__ c2 caddh(c2 a, c2 b) { return { a.x + b.x, a.y + b.y }; }

__global__ void tq_setup_kernel(const float* __restrict__ theta) {
    int t = threadIdx.x;
    if (t >= NL * NQ) return;
    float t0 = theta[t*3+0], t1 = theta[t*3+1], t2 = theta[t*3+2];
    float cx = cosf(0.5f*t0), sx = sinf(0.5f*t0);
    float cy = cosf(0.5f*t1), sy = sinf(0.5f*t1);
    float cz = cosf(0.5f*t2), sz = sinf(0.5f*t2);

    c2 x00{cx,0.f}, x01{0.f,-sx}, x10{0.f,-sx}, x11{cx,0.f};
    c2 y00{cy,0.f}, y01{-sy,0.f}, y10{sy,0.f},  y11{cy,0.f};

    c2 A00 = caddh(cmulh(x00,y00), cmulh(x01,y10));
    c2 A01 = caddh(cmulh(x00,y01), cmulh(x01,y11));
    c2 A10 = caddh(cmulh(x10,y00), cmulh(x11,y10));
    c2 A11 = caddh(cmulh(x10,y01), cmulh(x11,y11));

    c2 e0{cz,-sz}, e1{cz,sz};
    c2 M00 = cmulh(A00,e0), M01 = cmulh(A01,e1);
    c2 M10 = cmulh(A10,e0), M11 = cmulh(A11,e1);

    u64* o = &gPackedBuf[t * 24];
    for (int rlo = 0; rlo < 2; ++rlo)
        for (int rhi = 0; rhi < 2; ++rhi) {
            c2 Alo = rlo ? M11 : M00, Ahi = rhi ? M11 : M00;
            c2 Blo = rlo ? M01 : M10, Bhi = rhi ? M01 : M10;
            u64* p = o + (rlo * 2 + rhi) * 6;
            p[0] = pk2(Alo.x,  Ahi.x);
            p[1] = pk2(Alo.y,  Ahi.y);
            p[2] = pk2(-Alo.y, -Ahi.y);
            p[3] = pk2(Blo.x,  Bhi.x);
            p[4] = pk2(Blo.y,  Bhi.y);
            p[5] = pk2(-Blo.y, -Bhi.y);
        }

    if (t < NQ) {     // layer-0 raw matrices for init absorption
        float* m = &gM0Buf[t * 8];
        m[0] = M00.x; m[1] = M00.y; m[2] = M01.x; m[3] = M01.y;
        m[4] = M10.x; m[5] = M10.y; m[6] = M11.x; m[7] = M11.y;
    }
}

// ============================================================
// One gate, frame-tracked (identical to R13, which passed).
// ============================================================
#define CSEL(R, I) ((R) ? C1_##I : C0_##I)

#define UPDP(X, Y, PX, PY, R) do {                                            \
    u64 _nx = fma2((PY), CSEL(R,5), fma2((PX), CSEL(R,3),                     \
              fma2((Y),  CSEL(R,2), mul2((X),  CSEL(R,0)))));                 \
    u64 _ny = fma2((PY), CSEL(R,3), fma2((PX), CSEL(R,4),                     \
              fma2((Y),  CSEL(R,0), mul2((X),  CSEL(R,1)))));                 \
    (X) = _nx; (Y) = _ny; } while (0)

#define GJ_SELF(J) {                                                          \
    constexpr bool R_ = (selreg != 0) && (parc((J) & selreg) != 0);           \
    u64 px_ = xs[J], py_ = ys[J];                                             \
    if constexpr (mlane != 0) { px_ = shfl64x(px_, mlane);                    \
                                py_ = shfl64x(py_, mlane); }                  \
    if constexpr (mp == 1)    { px_ = swap64(px_); py_ = swap64(py_); }       \
    UPDP(xs[J], ys[J], px_, py_, R_); }

#define GJ_PAIR(J) if constexpr ((((J) & hb) == 0) && mreg != 0) {            \
    constexpr int  J2_ = (J) ^ mreg;                                         \
    constexpr bool RA_ = (selreg != 0) && (parc((J)  & selreg) != 0);         \
    constexpr bool RB_ = (selreg != 0) && (parc(J2_ & selreg) != 0);          \
    u64 pax_ = xs[J2_], pay_ = ys[J2_], pbx_ = xs[J], pby_ = ys[J];           \
    if constexpr (mlane != 0) {                                               \
        pax_ = shfl64x(pax_, mlane); pay_ = shfl64x(pay_, mlane);             \
        pbx_ = shfl64x(pbx_, mlane); pby_ = shfl64x(pby_, mlane); }           \
    if constexpr (mp == 1) {                                                  \
        pax_ = swap64(pax_); pay_ = swap64(pay_);                             \
        pbx_ = swap64(pbx_); pby_ = swap64(pby_); }                           \
    UPDP(xs[J],  ys[J],  pax_, pay_, RA_);                                    \
    UPDP(xs[J2_], ys[J2_], pbx_, pby_, RB_); }

template<int L, int P>
__device__ __forceinline__ void apply_gate(u64* xs, u64* ys, int lane) {
    constexpr int m  = MT.m[L][P];
    constexpr int sl = MT.sel[L][P];
    static_assert(parc(m & sl) == 1, "pair must flip role");
    constexpr int mp = (m >> 9) & 1, mreg = (m >> 5) & 15, mlane = m & 31;
    constexpr int sp = (sl >> 9) & 1, selreg = (sl >> 5) & 15, sellane = sl & 31;
    constexpr int g24 = (L * NQ + (9 - P)) * 24;
    constexpr int i0 = ((0 << 1) | (0 ^ sp)) * 6;
    constexpr int i1 = ((1 << 1) | (1 ^ sp)) * 6;
    constexpr int hb = mreg ? (mreg & (-mreg)) : 1;

    u64 C0_0, C0_1, C0_2, C0_3, C0_4, C0_5;
    u64 C1_0 = 0, C1_1 = 0, C1_2 = 0, C1_3 = 0, C1_4 = 0, C1_5 = 0;
    if constexpr (sellane != 0) {
        const bool lp = (__popc(lane & sellane) & 1) != 0;
        C0_0 = lp ? cG[g24+i1+0] : cG[g24+i0+0];
        C0_1 = lp ? cG[g24+i1+1] : cG[g24+i0+1];
        C0_2 = lp ? cG[g24+i1+2] : cG[g24+i0+2];
        C0_3 = lp ? cG[g24+i1+3] : cG[g24+i0+3];
        C0_4 = lp ? cG[g24+i1+4] : cG[g24+i0+4];
        C0_5 = lp ? cG[g24+i1+5] : cG[g24+i0+5];
        if constexpr (selreg != 0) {
            C1_0 = lp ? cG[g24+i0+0] : cG[g24+i1+0];
            C1_1 = lp ? cG[g24+i0+1] : cG[g24+i1+1];
            C1_2 = lp ? cG[g24+i0+2] : cG[g24+i1+2];
            C1_3 = lp ? cG[g24+i0+3] : cG[g24+i1+3];
            C1_4 = lp ? cG[g24+i0+4] : cG[g24+i1+4];
            C1_5 = lp ? cG[g24+i0+5] : cG[g24+i1+5];
        }
    } else {
        C0_0 = cG[g24+i0+0]; C0_1 = cG[g24+i0+1]; C0_2 = cG[g24+i0+2];
        C0_3 = cG[g24+i0+3]; C0_4 = cG[g24+i0+4]; C0_5 = cG[g24+i0+5];
        if constexpr (selreg != 0) {
            C1_0 = cG[g24+i1+0]; C1_1 = cG[g24+i1+1]; C1_2 = cG[g24+i1+2];
            C1_3 = cG[g24+i1+3]; C1_4 = cG[g24+i1+4]; C1_5 = cG[g24+i1+5];
        }
    }

    if constexpr (mreg == 0) {
        GJ_SELF(0)  GJ_SELF(1)  GJ_SELF(2)  GJ_SELF(3)
        GJ_SELF(4)  GJ_SELF(5)  GJ_SELF(6)  GJ_SELF(7)
        GJ_SELF(8)  GJ_SELF(9)  GJ_SELF(10) GJ_SELF(11)
        GJ_SELF(12) GJ_SELF(13) GJ_SELF(14) GJ_SELF(15)
    } else {
        GJ_PAIR(0)  GJ_PAIR(1)  GJ_PAIR(2)  GJ_PAIR(3)
        GJ_PAIR(4)  GJ_PAIR(5)  GJ_PAIR(6)  GJ_PAIR(7)
        GJ_PAIR(8)  GJ_PAIR(9)  GJ_PAIR(10) GJ_PAIR(11)
        GJ_PAIR(12) GJ_PAIR(13) GJ_PAIR(14) GJ_PAIR(15)
    }
}

// ============================================================
// Layers. Gates within a layer commute (disjoint qubits): order
// is free PER WARP. REV=false: R13 interleaved order. REV=true:
// reversed order. Odd warps run reversed -> at any instant half
// the warps are in a shuffle burst while the other half are in
// an FMA burst, de-phasing the MIO rendezvous.
// ============================================================
template<int L, bool REV>
__device__ __forceinline__ void layer(u64* xs, u64* ys, int lane) {
    if constexpr (L == 1) {
        if constexpr (!REV) {
            apply_gate<L, 5>(xs, ys, lane);
            apply_gate<L, 9>(xs, ys, lane);
            apply_gate<L, 4>(xs, ys, lane);
            apply_gate<L, 8>(xs, ys, lane);
            apply_gate<L, 3>(xs, ys, lane);
            apply_gate<L, 7>(xs, ys, lane);
            apply_gate<L, 2>(xs, ys, lane);
            apply_gate<L, 6>(xs, ys, lane);
            apply_gate<L, 1>(xs, ys, lane);
            apply_gate<L, 0>(xs, ys, lane);
        } else {
            apply_gate<L, 0>(xs, ys, lane);
            apply_gate<L, 1>(xs, ys, lane);
            apply_gate<L, 6>(xs, ys, lane);
            apply_gate<L, 2>(xs, ys, lane);
            apply_gate<L, 7>(xs, ys, lane);
            apply_gate<L, 3>(xs, ys, lane);
            apply_gate<L, 8>(xs, ys, lane);
            apply_gate<L, 4>(xs, ys, lane);
            apply_gate<L, 9>(xs, ys, lane);
            apply_gate<L, 5>(xs, ys, lane);
        }
    } else if constexpr (L == 2) {
        if constexpr (!REV) {
            apply_gate<L, 6>(xs, ys, lane);
            apply_gate<L, 9>(xs, ys, lane);
            apply_gate<L, 5>(xs, ys, lane);
            apply_gate<L, 8>(xs, ys, lane);
            apply_gate<L, 4>(xs, ys, lane);
            apply_gate<L, 7>(xs, ys, lane);
            apply_gate<L, 3>(xs, ys, lane);
            apply_gate<L, 2>(xs, ys, lane);
            apply_gate<L, 1>(xs, ys, lane);
            apply_gate<L, 0>(xs, ys, lane);
        } else {
            apply_gate<L, 0>(xs, ys, lane);
            apply_gate<L, 1>(xs, ys, lane);
            apply_gate<L, 2>(xs, ys, lane);
            apply_gate<L, 3>(xs, ys, lane);
            apply_gate<L, 7>(xs, ys, lane);
            apply_gate<L, 4>(xs, ys, lane);
            apply_gate<L, 8>(xs, ys, lane);
            apply_gate<L, 5>(xs, ys, lane);
            apply_gate<L, 9>(xs, ys, lane);
            apply_gate<L, 6>(xs, ys, lane);
        }
    } else {
        if constexpr (!REV) {
            apply_gate<L, 7>(xs, ys, lane);
            apply_gate<L, 9>(xs, ys, lane);
            apply_gate<L, 6>(xs, ys, lane);
            apply_gate<L, 8>(xs, ys, lane);
            apply_gate<L, 5>(xs, ys, lane);
            apply_gate<L, 4>(xs, ys, lane);
            apply_gate<L, 3>(xs, ys, lane);
            apply_gate<L, 2>(xs, ys, lane);
            apply_gate<L, 1>(xs, ys, lane);
            apply_gate<L, 0>(xs, ys, lane);
        } else {
            apply_gate<L, 0>(xs, ys, lane);
            apply_gate<L, 1>(xs, ys, lane);
            apply_gate<L, 2>(xs, ys, lane);
            apply_gate<L, 3>(xs, ys, lane);
            apply_gate<L, 4>(xs, ys, lane);
            apply_gate<L, 5>(xs, ys, lane);
            apply_gate<L, 8>(xs, ys, lane);
            apply_gate<L, 6>(xs, ys, lane);
            apply_gate<L, 9>(xs, ys, lane);
            apply_gate<L, 7>(xs, ys, lane);
        }
    }
}

// ============================================================
// Readout (unchanged from R13)
// ============================================================
template<int Q>
__device__ __forceinline__ float readout_one(const u64* pr, int lane) {
    constexpr int sel = MT.sel[NL][9 - Q];
    constexpr int sp  = (sel >> 9) & 1;
    constexpr int sr  = (sel >> 5) & 15;
    constexpr int slq = sel & 31;
    const u64 sPP = pk2(1.f,  sp ? -1.f : 1.f);
    const u64 sNN = pk2(-1.f, sp ? 1.f : -1.f);
    u64 acc = pk2(0.f, 0.f);
#pragma unroll
    for (int j = 0; j < 16; ++j)
        acc = fma2(pr[j], parc(j & sr) ? sNN : sPP, acc);
    float lo, hi; upk(acc, lo, hi);
    float a = lo + hi;
    if constexpr (slq != 0) {
        if (__popc(lane & slq) & 1) a = -a;
    }
#pragma unroll
    for (int off = 16; off; off >>= 1)
        a += __shfl_xor_sync(0xffffffffu, a, off);
    return a;
}

// ============================================================
// Main kernel: layer 0 absorbed into init; per-warp-parity order
// ============================================================
__global__ __launch_bounds__(BLOCK, 4)
void tq_main_kernel(const float* __restrict__ x,
                    const float* __restrict__ W,
                    const float* __restrict__ bias,
                    float* __restrict__ out) {
    const int lane = threadIdx.x & 31;
    const int wid  = threadIdx.x >> 5;
    const int b    = blockIdx.x * WPB + wid;

    // per-qubit post-layer-0 2-vectors: v_q = (cos,-sin) @ M0_q  (complex)
    float2 v0[NQ], v1[NQ];
    {
        float x0 = x[b*3+0], x1 = x[b*3+1], x2 = x[b*3+2];
#pragma unroll
        for (int q = 0; q < NQ; ++q) {
            float z = fmaf(x0, W[q*3+0], fmaf(x1, W[q*3+1], fmaf(x2, W[q*3+2], bias[q])));
            float t = 3.14159265358979323846f * tanhf(z);
            float s, c; sincosf(0.5f * t, &s, &c);
            const float* mm = &cM0[q * 8];
            v0[q].x = fmaf(c, mm[0], -s * mm[4]);
            v0[q].y = fmaf(c, mm[1], -s * mm[5]);
            v1[q].x = fmaf(c, mm[2], -s * mm[6]);
            v1[q].y = fmaf(c, mm[3], -s * mm[7]);
        }
    }

    // complex product-state build
    u64 xs[16], ys[16];
    {
        float2 F = (lane & 1) ? v1[9] : v0[9];
#pragma unroll
        for (int p = 1; p < 5; ++p) {
            float2 g = ((lane >> p) & 1) ? v1[9 - p] : v0[9 - p];
            F = make_float2(F.x * g.x - F.y * g.y, F.x * g.y + F.y * g.x);
        }
        float2 af[16];
        af[0] = F;
#pragma unroll
        for (int bit = 0; bit < 4; ++bit) {
            int q = 4 - bit;
#pragma unroll
            for (int k = (1 << bit) - 1; k >= 0; --k) {
                float2 a = af[k];
                af[k | (1 << bit)] = make_float2(a.x * v1[q].x - a.y * v1[q].y,
                                                 a.x * v1[q].y + a.y * v1[q].x);
                af[k]              = make_float2(a.x * v0[q].x - a.y * v0[q].y,
                                                 a.x * v0[q].y + a.y * v0[q].x);
            }
        }
#pragma unroll
        for (int j = 0; j < 16; ++j) {
            float2 a = af[j];
            float lox = a.x * v0[0].x - a.y * v0[0].y;
            float loy = a.x * v0[0].y + a.y * v0[0].x;
            float hix = a.x * v1[0].x - a.y * v1[0].y;
            float hiy = a.x * v1[0].y + a.y * v1[0].x;
            xs[j] = pk2(lox, hix);
            ys[j] = pk2(loy, hiy);
        }
    }

    // De-phased schedules: odd warps run each layer's gates reversed.
    if (wid & 1) {
        layer<1, true>(xs, ys, lane);
        layer<2, true>(xs, ys, lane);
        layer<3, true>(xs, ys, lane);
    } else {
        layer<1, false>(xs, ys, lane);
        layer<2, false>(xs, ys, lane);
        layer<3, false>(xs, ys, lane);
    }

#pragma unroll
    for (int j = 0; j < 16; ++j)
        xs[j] = fma2(ys[j], ys[j], mul2(xs[j], xs[j]));

    float e[NQ];
    e[0] = readout_one<0>(xs, lane);
    e[1] = readout_one<1>(xs, lane);
    e[2] = readout_one<2>(xs, lane);
    e[3] = readout_one<3>(xs, lane);
    e[4] = readout_one<4>(xs, lane);
    e[5] = readout_one<5>(xs, lane);
    e[6] = readout_one<6>(xs, lane);
    e[7] = readout_one<7>(xs, lane);
    e[8] = readout_one<8>(xs, lane);
    e[9] = readout_one<9>(xs, lane);

    if (lane == 0) {
#pragma unroll
        for (int q = 0; q < NQ; ++q) out[b * NQ + q] = e[q];
    }
}

extern "C" void kernel_launch(void* const* d_in, const int* in_sizes, int n_in,
                              void* d_out, int out_size) {
    const float* x     = (const float*)d_in[0];   // [16384, 3]
    const float* enc_W = (const float*)d_in[1];   // [10, 3]
    const float* enc_b = (const float*)d_in[2];   // [10]
    const float* theta = (const float*)d_in[3];   // [4, 10, 3]
    float* out = (float*)d_out;                   // [16384, 10]

    int batch = in_sizes[0] / 3;

    tq_setup_kernel<<<1, 64>>>(theta);

    void* src = nullptr;
    cudaGetSymbolAddress(&src, gPackedBuf);
    cudaMemcpyToSymbolAsync(cG, src, sizeof(u64) * NL * NQ * 24, 0,
                            cudaMemcpyDeviceToDevice, 0);
    void* src0 = nullptr;
    cudaGetSymbolAddress(&src0, gM0Buf);
    cudaMemcpyToSymbolAsync(cM0, src0, sizeof(float) * NQ * 8, 0,
                            cudaMemcpyDeviceToDevice, 0);

    tq_main_kernel<<<batch / WPB, BLOCK>>>(x, enc_W, enc_b, out);
}

// round 16
// speedup vs baseline: 1.1459x; 1.1459x over previous
#include <cuda_runtime.h>

#define NQ     10
#define NL     4
#define WPB    4
#define BLOCK  (32 * WPB)

typedef unsigned long long u64;

// Per gate: 6 SPLAT packs {Car,Cai,CaiN,Cbr,Cbi,CbrN} with a=M00, b=M10 (SU2)
__device__   u64 gPackedBuf[NL * NQ * 6];
__constant__ u64 cG[NL * NQ * 6];
// Layer-0 fused matrices, plain floats: {M00x,M00y,M01x,M01y,M10x,M10y,M11x,M11y}
__device__   float gM0Buf[NQ * 8];
__constant__ float cM0[NQ * 8];

// ============================================================
// Compile-time GF(2) frame tables (semantics verified R8-R13)
// ============================================================
__host__ __device__ constexpr int parc(int v) {
    int c = 0;
    for (int b = 0; b < NQ; ++b) c ^= (v >> b) & 1;
    return c;
}

constexpr int sigma1(int j) {
    int s = j;
    for (int q = 9; q >= 0; --q) {
        int pc = 9 - q;
        int pt = 9 - ((q + 1) % 10);
        s ^= ((s >> pc) & 1) << pt;
    }
    return s;
}

struct MaskTab {
    int m[NL][NQ];
    int sel[NL + 1][NQ];
};

constexpr MaskTab build_masks() {
    MaskTab t{};
    int perm[1024] = {};
    for (int j = 0; j < 1024; ++j) perm[j] = j;
    int inv[1024] = {};
    for (int l = 0; l <= NL; ++l) {
        if (l < NL)
            for (int p = 0; p < NQ; ++p) t.m[l][p] = perm[1 << p];
        for (int j = 0; j < 1024; ++j) inv[perm[j]] = j;
        for (int p = 0; p < NQ; ++p) {
            int s = 0;
            for (int b = 0; b < NQ; ++b) s |= ((inv[1 << b] >> p) & 1) << b;
            t.sel[l][p] = s;
        }
        if (l < NL) {
            int nxt[1024] = {};
            for (int j = 0; j < 1024; ++j) nxt[j] = perm[sigma1(j)];
            for (int j = 0; j < 1024; ++j) perm[j] = nxt[j];
        }
    }
    return t;
}
constexpr MaskTab MT = build_masks();

// Sign mask for (reg-part, pack-part) of a parity functional at pack index J:
// bit31 set iff parity of lo-amp, bit63 iff parity of hi-amp.
__host__ __device__ constexpr u64 kmask_sign(int creg, int cp, int J) {
    int lo = parc(J & creg);
    int hi = lo ^ (cp & 1);
    return (lo ? 0x80000000ull : 0ull) | (hi ? 0x8000000000000000ull : 0ull);
}

// ============================================================
// Packed f32x2 helpers
// ============================================================
__device__ __forceinline__ u64 pk2(float a, float b) {
    u64 r; asm("mov.b64 %0, {%1, %2};" : "=l"(r) : "f"(a), "f"(b)); return r;
}
__device__ __forceinline__ void upk(u64 v, float& a, float& b) {
    asm("mov.b64 {%0, %1}, %2;" : "=f"(a), "=f"(b) : "l"(v));
}
__device__ __forceinline__ u64 fma2(u64 a, u64 b, u64 c) {
    u64 d; asm("fma.rn.f32x2 %0, %1, %2, %3;" : "=l"(d) : "l"(a), "l"(b), "l"(c)); return d;
}
__device__ __forceinline__ u64 mul2(u64 a, u64 b) {
    u64 d; asm("mul.rn.f32x2 %0, %1, %2;" : "=l"(d) : "l"(a), "l"(b)); return d;
}
__device__ __forceinline__ u64 swap64(u64 v) {
    union { u64 w; uint2 u; } a;
    a.w = v;
    unsigned t = a.u.x; a.u.x = a.u.y; a.u.y = t;
    return a.w;
}
__device__ __forceinline__ u64 shfl64x(u64 v, int xm) {
    return __shfl_xor_sync(0xffffffffu, v, xm);
}

// ============================================================
// Setup: fuse Rx*Ry*Rz; SU2 splat packs + raw M for layer 0
// ============================================================
struct c2 { float x, y; };
__device__ __forceinline__ c2 cmulh(c2 a, c2 b) { return { a.x*b.x - a.y*b.y, a.x*b.y + a.y*b.x }; }
__device__ __forceinline__ c2 caddh(c2 a, c2 b) { return { a.x + b.x, a.y + b.y }; }

__global__ void tq_setup_kernel(const float* __restrict__ theta) {
    int t = threadIdx.x;
    if (t >= NL * NQ) return;
    float t0 = theta[t*3+0], t1 = theta[t*3+1], t2 = theta[t*3+2];
    float cx = cosf(0.5f*t0), sx = sinf(0.5f*t0);
    float cy = cosf(0.5f*t1), sy = sinf(0.5f*t1);
    float cz = cosf(0.5f*t2), sz = sinf(0.5f*t2);

    c2 x00{cx,0.f}, x01{0.f,-sx}, x10{0.f,-sx}, x11{cx,0.f};
    c2 y00{cy,0.f}, y01{-sy,0.f}, y10{sy,0.f},  y11{cy,0.f};

    c2 A00 = caddh(cmulh(x00,y00), cmulh(x01,y10));
    c2 A01 = caddh(cmulh(x00,y01), cmulh(x01,y11));
    c2 A10 = caddh(cmulh(x10,y00), cmulh(x11,y10));
    c2 A11 = caddh(cmulh(x10,y01), cmulh(x11,y11));

    c2 e0{cz,-sz}, e1{cz,sz};
    c2 M00 = cmulh(A00,e0), M01 = cmulh(A01,e1);
    c2 M10 = cmulh(A10,e0), M11 = cmulh(A11,e1);

    // SU(2): only a=M00, b=M10 needed; splat packs (warp-uniform)
    u64* o = &gPackedBuf[t * 6];
    o[0] = pk2(M00.x,  M00.x);   // Car
    o[1] = pk2(M00.y,  M00.y);   // Cai
    o[2] = pk2(-M00.y, -M00.y);  // CaiN
    o[3] = pk2(M10.x,  M10.x);   // Cbr
    o[4] = pk2(M10.y,  M10.y);   // Cbi
    o[5] = pk2(-M10.x, -M10.x);  // CbrN

    if (t < NQ) {     // layer-0 raw matrices for init absorption
        float* m = &gM0Buf[t * 8];
        m[0] = M00.x; m[1] = M00.y; m[2] = M01.x; m[3] = M01.y;
        m[4] = M10.x; m[5] = M10.y; m[6] = M11.x; m[7] = M11.y;
    }
}

// ============================================================
// Gate in sign-gauge form. State: xs[16] (true re), ys[16]
// (gauged im: ystored = (-1)^{<G,i>} y_true, G = sel of the last
// applied gate; G=0 after init). Update (re-verified both roles):
//   nx = x*ar - yt*ai + Px*br + Py*bi
//   ny = x*ai + yt*ar + Px*bi - Py*br
// with (Px,Py) = (-1)^{<sel,i>} * partner's stored (x, yt).
// ============================================================
#define G2_SELF(J) {                                                          \
    constexpr u64 KS_ = kmask_sign(selreg, sp, (J));                          \
    u64 px_ = xs[J], py_ = ys[J];                                             \
    if constexpr (mlane != 0) { px_ = shfl64x(px_, mlane);                    \
                                py_ = shfl64x(py_, mlane); }                  \
    if constexpr (mp == 1)    { px_ = swap64(px_); py_ = swap64(py_); }       \
    px_ ^= (bmS ^ KS_);  py_ ^= (bmS ^ KS_);                                  \
    u64 nx_ = fma2(py_, Cbi,  fma2(px_, Cbr, fma2(ys[J], CaiN, mul2(xs[J], Car)))); \
    u64 ny_ = fma2(py_, CbrN, fma2(px_, Cbi, fma2(ys[J], Car,  mul2(xs[J], Cai)))); \
    xs[J] = nx_; ys[J] = ny_; }

#define G2_PAIR(J) if constexpr ((((J) & hb) == 0) && mreg != 0) {            \
    constexpr int J2_ = (J) ^ mreg;                                           \
    constexpr u64 KSa = kmask_sign(selreg, sp, (J));                          \
    constexpr u64 KSb = kmask_sign(selreg, sp, J2_);                          \
    u64 pax = xs[J2_], pay = ys[J2_], pbx = xs[J], pby = ys[J];               \
    if constexpr (mlane != 0) {                                               \
        pax = shfl64x(pax, mlane); pay = shfl64x(pay, mlane);                 \
        pbx = shfl64x(pbx, mlane); pby = shfl64x(pby, mlane); }               \
    if constexpr (mp == 1) {                                                  \
        pax = swap64(pax); pay = swap64(pay);                                 \
        pbx = swap64(pbx); pby = swap64(pby); }                               \
    pax ^= (bmS ^ KSa);  pay ^= (bmS ^ KSa);                                  \
    pbx ^= (bmS ^ KSb);  pby ^= (bmS ^ KSb);                                  \
    u64 nxa = fma2(pay, Cbi,  fma2(pax, Cbr, fma2(ys[J],  CaiN, mul2(xs[J],  Car)))); \
    u64 nya = fma2(pay, CbrN, fma2(pax, Cbi, fma2(ys[J],  Car,  mul2(xs[J],  Cai)))); \
    u64 nxb = fma2(pby, Cbi,  fma2(pbx, Cbr, fma2(ys[J2_], CaiN, mul2(xs[J2_], Car)))); \
    u64 nyb = fma2(pby, CbrN, fma2(pbx, Cbi, fma2(ys[J2_], Car,  mul2(xs[J2_], Cai)))); \
    xs[J] = nxa; ys[J] = nya; xs[J2_] = nxb; ys[J2_] = nyb; }

#define REGAUGE(J) {                                                          \
    constexpr u64 KD_ = kmask_sign(Dreg, Dp, (J));                            \
    if constexpr (Dlane != 0)      ys[J] ^= (bmD ^ KD_);                      \
    else if constexpr (KD_ != 0ull) ys[J] ^= KD_; }

template<int SELPREV, int L, int P>
__device__ __forceinline__ void gate2(u64* xs, u64* ys, int lane) {
    constexpr int m  = MT.m[L][P];
    constexpr int sl = MT.sel[L][P];
    static_assert(parc(m & sl) == 1, "pair must flip role");
    constexpr int mp = (m >> 9) & 1, mreg = (m >> 5) & 15, mlane = m & 31;
    constexpr int sp = (sl >> 9) & 1, selreg = (sl >> 5) & 15, sellane = sl & 31;
    constexpr int D  = sl ^ SELPREV;
    constexpr int Dp = (D >> 9) & 1, Dreg = (D >> 5) & 15, Dlane = D & 31;
    constexpr int g6 = (L * NQ + (9 - P)) * 6;
    constexpr int hb = mreg ? (mreg & (-mreg)) : 1;

    // warp-uniform splat coefficients (no per-lane selects)
    const u64 Car  = cG[g6+0], Cai  = cG[g6+1], CaiN = cG[g6+2];
    const u64 Cbr  = cG[g6+3], Cbi  = cG[g6+4], CbrN = cG[g6+5];

    // re-gauge ys from gauge SELPREV to gauge sl
    u64 bmD = 0;
    if constexpr (Dlane != 0)
        bmD = (__popc(lane & Dlane) & 1) ? 0x8000000080000000ull : 0ull;
    REGAUGE(0)  REGAUGE(1)  REGAUGE(2)  REGAUGE(3)
    REGAUGE(4)  REGAUGE(5)  REGAUGE(6)  REGAUGE(7)
    REGAUGE(8)  REGAUGE(9)  REGAUGE(10) REGAUGE(11)
    REGAUGE(12) REGAUGE(13) REGAUGE(14) REGAUGE(15)

    // epsilon base mask (lane component of <sel, i>)
    u64 bmS = 0;
    if constexpr (sellane != 0)
        bmS = (__popc(lane & sellane) & 1) ? 0x8000000080000000ull : 0ull;

    if constexpr (mreg == 0) {
        G2_SELF(0)  G2_SELF(1)  G2_SELF(2)  G2_SELF(3)
        G2_SELF(4)  G2_SELF(5)  G2_SELF(6)  G2_SELF(7)
        G2_SELF(8)  G2_SELF(9)  G2_SELF(10) G2_SELF(11)
        G2_SELF(12) G2_SELF(13) G2_SELF(14) G2_SELF(15)
    } else {
        G2_PAIR(0)  G2_PAIR(1)  G2_PAIR(2)  G2_PAIR(3)
        G2_PAIR(4)  G2_PAIR(5)  G2_PAIR(6)  G2_PAIR(7)
        G2_PAIR(8)  G2_PAIR(9)  G2_PAIR(10) G2_PAIR(11)
        G2_PAIR(12) G2_PAIR(13) G2_PAIR(14) G2_PAIR(15)
    }
}

// R13 interleaved order; gauge chained through SELPREV (init gauge = 0)
__device__ __forceinline__ void run_layers(u64* xs, u64* ys, int lane) {
    gate2<0,            1, 5>(xs, ys, lane);
    gate2<MT.sel[1][5], 1, 9>(xs, ys, lane);
    gate2<MT.sel[1][9], 1, 4>(xs, ys, lane);
    gate2<MT.sel[1][4], 1, 8>(xs, ys, lane);
    gate2<MT.sel[1][8], 1, 3>(xs, ys, lane);
    gate2<MT.sel[1][3], 1, 7>(xs, ys, lane);
    gate2<MT.sel[1][7], 1, 2>(xs, ys, lane);
    gate2<MT.sel[1][2], 1, 6>(xs, ys, lane);
    gate2<MT.sel[1][6], 1, 1>(xs, ys, lane);
    gate2<MT.sel[1][1], 1, 0>(xs, ys, lane);

    gate2<MT.sel[1][0], 2, 6>(xs, ys, lane);
    gate2<MT.sel[2][6], 2, 9>(xs, ys, lane);
    gate2<MT.sel[2][9], 2, 5>(xs, ys, lane);
    gate2<MT.sel[2][5], 2, 8>(xs, ys, lane);
    gate2<MT.sel[2][8], 2, 4>(xs, ys, lane);
    gate2<MT.sel[2][4], 2, 7>(xs, ys, lane);
    gate2<MT.sel[2][7], 2, 3>(xs, ys, lane);
    gate2<MT.sel[2][3], 2, 2>(xs, ys, lane);
    gate2<MT.sel[2][2], 2, 1>(xs, ys, lane);
    gate2<MT.sel[2][1], 2, 0>(xs, ys, lane);

    gate2<MT.sel[2][0], 3, 7>(xs, ys, lane);
    gate2<MT.sel[3][7], 3, 9>(xs, ys, lane);
    gate2<MT.sel[3][9], 3, 6>(xs, ys, lane);
    gate2<MT.sel[3][6], 3, 8>(xs, ys, lane);
    gate2<MT.sel[3][8], 3, 5>(xs, ys, lane);
    gate2<MT.sel[3][5], 3, 4>(xs, ys, lane);
    gate2<MT.sel[3][4], 3, 3>(xs, ys, lane);
    gate2<MT.sel[3][3], 3, 2>(xs, ys, lane);
    gate2<MT.sel[3][2], 3, 1>(xs, ys, lane);
    gate2<MT.sel[3][1], 3, 0>(xs, ys, lane);
}

// ============================================================
// Readout: |x|^2 + |ystored|^2 = |x|^2 + |y|^2 (gauge-free)
// ============================================================
template<int Q>
__device__ __forceinline__ float readout_one(const u64* pr, int lane) {
    constexpr int sel = MT.sel[NL][9 - Q];
    constexpr int sp  = (sel >> 9) & 1;
    constexpr int sr  = (sel >> 5) & 15;
    constexpr int slq = sel & 31;
    const u64 sPP = pk2(1.f,  sp ? -1.f : 1.f);
    const u64 sNN = pk2(-1.f, sp ? 1.f : -1.f);
    u64 acc = pk2(0.f, 0.f);
#pragma unroll
    for (int j = 0; j < 16; ++j)
        acc = fma2(pr[j], parc(j & sr) ? sNN : sPP, acc);
    float lo, hi; upk(acc, lo, hi);
    float a = lo + hi;
    if constexpr (slq != 0) {
        if (__popc(lane & slq) & 1) a = -a;
    }
#pragma unroll
    for (int off = 16; off; off >>= 1)
        a += __shfl_xor_sync(0xffffffffu, a, off);
    return a;
}

// ============================================================
// Main kernel: layer 0 absorbed into init; SU2 gauge gates
// ============================================================
__global__ __launch_bounds__(BLOCK, 4)
void tq_main_kernel(const float* __restrict__ x,
                    const float* __restrict__ W,
                    const float* __restrict__ bias,
                    float* __restrict__ out) {
    const int lane = threadIdx.x & 31;
    const int b    = blockIdx.x * WPB + (threadIdx.x >> 5);

    // per-qubit post-layer-0 2-vectors: v_q = (cos,-sin) @ M0_q  (complex)
    float2 v0[NQ], v1[NQ];
    {
        float x0 = x[b*3+0], x1 = x[b*3+1], x2 = x[b*3+2];
#pragma unroll
        for (int q = 0; q < NQ; ++q) {
            float z = fmaf(x0, W[q*3+0], fmaf(x1, W[q*3+1], fmaf(x2, W[q*3+2], bias[q])));
            float t = 3.14159265358979323846f * tanhf(z);
            float s, c; sincosf(0.5f * t, &s, &c);
            const float* mm = &cM0[q * 8];
            v0[q].x = fmaf(c, mm[0], -s * mm[4]);
            v0[q].y = fmaf(c, mm[1], -s * mm[5]);
            v1[q].x = fmaf(c, mm[2], -s * mm[6]);
            v1[q].y = fmaf(c, mm[3], -s * mm[7]);
        }
    }

    // complex product-state build (true values; gauge = 0)
    u64 xs[16], ys[16];
    {
        float2 F = (lane & 1) ? v1[9] : v0[9];
#pragma unroll
        for (int p = 1; p < 5; ++p) {
            float2 g = ((lane >> p) & 1) ? v1[9 - p] : v0[9 - p];
            F = make_float2(F.x * g.x - F.y * g.y, F.x * g.y + F.y * g.x);
        }
        float2 af[16];
        af[0] = F;
#pragma unroll
        for (int bit = 0; bit < 4; ++bit) {
            int q = 4 - bit;
#pragma unroll
            for (int k = (1 << bit) - 1; k >= 0; --k) {
                float2 a = af[k];
                af[k | (1 << bit)] = make_float2(a.x * v1[q].x - a.y * v1[q].y,
                                                 a.x * v1[q].y + a.y * v1[q].x);
                af[k]              = make_float2(a.x * v0[q].x - a.y * v0[q].y,
                                                 a.x * v0[q].y + a.y * v0[q].x);
            }
        }
#pragma unroll
        for (int j = 0; j < 16; ++j) {
            float2 a = af[j];
            float lox = a.x * v0[0].x - a.y * v0[0].y;
            float loy = a.x * v0[0].y + a.y * v0[0].x;
            float hix = a.x * v1[0].x - a.y * v1[0].y;
            float hiy = a.x * v1[0].y + a.y * v1[0].x;
            xs[j] = pk2(lox, hix);
            ys[j] = pk2(loy, hiy);
        }
    }

    run_layers(xs, ys, lane);

    // packed probabilities in place (gauge cancels in squares)
#pragma unroll
    for (int j = 0; j < 16; ++j)
        xs[j] = fma2(ys[j], ys[j], mul2(xs[j], xs[j]));

    float e[NQ];
    e[0] = readout_one<0>(xs, lane);
    e[1] = readout_one<1>(xs, lane);
    e[2] = readout_one<2>(xs, lane);
    e[3] = readout_one<3>(xs, lane);
    e[4] = readout_one<4>(xs, lane);
    e[5] = readout_one<5>(xs, lane);
    e[6] = readout_one<6>(xs, lane);
    e[7] = readout_one<7>(xs, lane);
    e[8] = readout_one<8>(xs, lane);
    e[9] = readout_one<9>(xs, lane);

    if (lane == 0) {
#pragma unroll
        for (int q = 0; q < NQ; ++q) out[b * NQ + q] = e[q];
    }
}

extern "C" void kernel_launch(void* const* d_in, const int* in_sizes, int n_in,
                              void* d_out, int out_size) {
    const float* x     = (const float*)d_in[0];   // [16384, 3]
    const float* enc_W = (const float*)d_in[1];   // [10, 3]
    const float* enc_b = (const float*)d_in[2];   // [10]
    const float* theta = (const float*)d_in[3];   // [4, 10, 3]
    float* out = (float*)d_out;                   // [16384, 10]

    int batch = in_sizes[0] / 3;

    tq_setup_kernel<<<1, 64>>>(theta);

    void* src = nullptr;
    cudaGetSymbolAddress(&src, gPackedBuf);
    cudaMemcpyToSymbolAsync(cG, src, sizeof(u64) * NL * NQ * 6, 0,
                            cudaMemcpyDeviceToDevice, 0);
    void* src0 = nullptr;
    cudaGetSymbolAddress(&src0, gM0Buf);
    cudaMemcpyToSymbolAsync(cM0, src0, sizeof(float) * NQ * 8, 0,
                            cudaMemcpyDeviceToDevice, 0);

    tq_main_kernel<<<batch / WPB, BLOCK>>>(x, enc_W, enc_b, out);
}